// round 11
// baseline (speedup 1.0000x reference)
#include <cuda_runtime.h>
#include <cuda_fp16.h>
#include <cstdint>

#define N_NODES 50000
#define N_EDGES 800000
#define D 128
#define N_GRAPHS 128
#define LN_EPS 1e-5f

// ==================== device scratch ====================
__device__ uint2 g_t2[N_NODES * 32];     // messages, fp16: 128 ch = 256B per node
__device__ float g_h[N_NODES * D];       // node state (fp32)
__device__ int   g_cnt[N_NODES];
__device__ float g_dinv[N_NODES];
__device__ int   g_rowoff[N_NODES + 1];
__device__ int   g_cursor[N_NODES];
__device__ int   g_srcs[N_EDGES];        // CSR src ids
__device__ float g_ew[N_EDGES];          // CSR edge weights (layer-invariant)

__device__ __forceinline__ float tf32r(float v) {
    uint32_t t;
    asm("cvt.rna.tf32.f32 %0, %1;" : "=r"(t) : "f"(v));
    return __uint_as_float(t);
}

__device__ __forceinline__ uint32_t pack_h2(float a, float b) {
    __half2 h = __floats2half2_rn(a, b);
    return *reinterpret_cast<uint32_t*>(&h);
}

__device__ __forceinline__ float2 h2f(uint32_t u) {
    return __half22float2(*reinterpret_cast<__half2*>(&u));
}

__device__ __forceinline__ void acc_row(float* acc, uint4 v, float w) {
    float2 q0 = h2f(v.x), q1 = h2f(v.y), q2 = h2f(v.z), q3 = h2f(v.w);
    acc[0] += q0.x * w; acc[1] += q0.y * w;
    acc[2] += q1.x * w; acc[3] += q1.y * w;
    acc[4] += q2.x * w; acc[5] += q2.y * w;
    acc[6] += q3.x * w; acc[7] += q3.y * w;
}

// ==================== CSR build ====================
__global__ void zero_cnt_kernel() {
    int i = blockIdx.x * blockDim.x + threadIdx.x;
    if (i < N_NODES) g_cnt[i] = 0;
}

__global__ void count_kernel(const int* __restrict__ edge_index) {
    int e = blockIdx.x * blockDim.x + threadIdx.x;
    if (e < N_EDGES) atomicAdd(&g_cnt[edge_index[N_EDGES + e]], 1);
}

__global__ void scan_kernel() {
    __shared__ int psum[1024];
    int t = threadIdx.x;
    const int CH = (N_NODES + 1023) / 1024;
    int base = t * CH, s = 0;
    for (int i = 0; i < CH; i++) {
        int idx = base + i;
        if (idx < N_NODES) s += g_cnt[idx];
    }
    psum[t] = s;
    __syncthreads();
    for (int o = 1; o < 1024; o <<= 1) {
        int v = 0;
        if (t >= o) v = psum[t - o];
        __syncthreads();
        psum[t] += v;
        __syncthreads();
    }
    int run = (t == 0) ? 0 : psum[t - 1];
    for (int i = 0; i < CH; i++) {
        int idx = base + i;
        if (idx < N_NODES) {
            int c = g_cnt[idx];
            g_rowoff[idx] = run;
            run += c;
            g_cursor[idx] = 0;
            g_dinv[idx] = rsqrtf((float)(c + 1));
        }
    }
    if (t == 1023) g_rowoff[N_NODES] = psum[1023];
}

__global__ void fill_kernel(const int* __restrict__ edge_index) {
    int e = blockIdx.x * blockDim.x + threadIdx.x;
    if (e < N_EDGES) {
        int s = edge_index[e];
        int d = edge_index[N_EDGES + e];
        int pos = g_rowoff[d] + atomicAdd(&g_cursor[d], 1);
        g_srcs[pos] = s;
        g_ew[pos] = g_dinv[s] * g_dinv[d];
    }
}

// ==================== tensor-core GEMM via mma.sync (tf32) ====================
// C[64x128] per CTA (BM=64), K=128 resident. smem ~101KB -> 2 CTAs/SM.
// 8 warps: 2(M) x 4(N), warp tile 32x32 = 2x4 m16n8k8 fragments.
#define BM 64
#define PAD 132

__global__ void __launch_bounds__(256, 2) gemm_mma_kernel(const float* __restrict__ A,
                                                          const float* __restrict__ W) {
    extern __shared__ float sm[];
    float* As = sm;               // [64][PAD]  (m, k)
    float* Ws = sm + BM * PAD;    // [128][PAD] (k, n) -- W as stored
    int tid = threadIdx.x;
    int r0 = blockIdx.x * BM;

    // stage W (k-major, coalesced float4, conflict-free) with tf32 round
    {
        const float4* W4 = (const float4*)W;
#pragma unroll
        for (int i = 0; i < 16; i++) {
            int idx = tid + i * 256;          // 4096 float4
            int k = idx >> 5, n4 = idx & 31;
            float4 v = W4[idx];
            v.x = tf32r(v.x); v.y = tf32r(v.y); v.z = tf32r(v.z); v.w = tf32r(v.w);
            *(float4*)&Ws[k * PAD + n4 * 4] = v;
        }
    }
    // stage A tile 64x128 (tf32-round on the fly)
    {
        const float4* A4 = (const float4*)A;
#pragma unroll
        for (int i = 0; i < 8; i++) {
            int idx = tid + i * 256;          // 2048 float4
            int m = idx >> 5, k4 = idx & 31;
            float4 v = make_float4(0.f, 0.f, 0.f, 0.f);
            if (r0 + m < N_NODES) v = A4[(r0 + m) * 32 + k4];
            v.x = tf32r(v.x); v.y = tf32r(v.y); v.z = tf32r(v.z); v.w = tf32r(v.w);
            *(float4*)&As[m * PAD + k4 * 4] = v;
        }
    }
    __syncthreads();

    int lane = tid & 31, wid = tid >> 5;
    int wm = (wid & 1) * 32;
    int wn = (wid >> 1) * 32;
    int gq = lane >> 2, tq = lane & 3;

    float acc[2][4][4];
#pragma unroll
    for (int mf = 0; mf < 2; mf++)
#pragma unroll
        for (int nf = 0; nf < 4; nf++)
#pragma unroll
            for (int j = 0; j < 4; j++) acc[mf][nf][j] = 0.f;

#pragma unroll
    for (int k0 = 0; k0 < 128; k0 += 8) {
        uint32_t a[2][4];
#pragma unroll
        for (int mf = 0; mf < 2; mf++) {
            const float* ap = &As[(wm + mf * 16 + gq) * PAD + k0 + tq];
            a[mf][0] = __float_as_uint(ap[0]);
            a[mf][2] = __float_as_uint(ap[4]);
            a[mf][1] = __float_as_uint(ap[8 * PAD]);
            a[mf][3] = __float_as_uint(ap[8 * PAD + 4]);
        }
        uint32_t b[4][2];
#pragma unroll
        for (int nf = 0; nf < 4; nf++) {
            const float* bp = &Ws[(k0 + tq) * PAD + wn + nf * 8 + gq];
            b[nf][0] = __float_as_uint(bp[0]);
            b[nf][1] = __float_as_uint(bp[4 * PAD]);
        }
#pragma unroll
        for (int mf = 0; mf < 2; mf++)
#pragma unroll
            for (int nf = 0; nf < 4; nf++) {
                asm volatile(
                    "mma.sync.aligned.m16n8k8.row.col.f32.tf32.tf32.f32 "
                    "{%0,%1,%2,%3}, {%4,%5,%6,%7}, {%8,%9}, {%0,%1,%2,%3};"
                    : "+f"(acc[mf][nf][0]), "+f"(acc[mf][nf][1]),
                      "+f"(acc[mf][nf][2]), "+f"(acc[mf][nf][3])
                    : "r"(a[mf][0]), "r"(a[mf][1]), "r"(a[mf][2]), "r"(a[mf][3]),
                      "r"(b[nf][0]), "r"(b[nf][1]));
            }
    }

    uint32_t* T = (uint32_t*)g_t2;
#pragma unroll
    for (int mf = 0; mf < 2; mf++) {
        int row0 = r0 + wm + mf * 16 + gq;
#pragma unroll
        for (int nf = 0; nf < 4; nf++) {
            int c2 = (wn + nf * 8 + 2 * tq) >> 1;
            if (row0 < N_NODES)
                T[row0 * 64 + c2] = pack_h2(acc[mf][nf][0], acc[mf][nf][1]);
            if (row0 + 8 < N_NODES)
                T[(row0 + 8) * 64 + c2] = pack_h2(acc[mf][nf][2], acc[mf][nf][3]);
        }
    }
}

// ==================== aggregation: HALF-WARP per node ====================
__global__ void __launch_bounds__(256) agg_kernel(const float* __restrict__ bias,
                                                  const float* __restrict__ gamma,
                                                  const float* __restrict__ beta,
                                                  int mode) {
    int t = blockIdx.x * blockDim.x + threadIdx.x;
    int n = t >> 4;
    int hl = threadIdx.x & 15;
    if (n >= N_NODES) return;

    float dn = g_dinv[n];
    const uint4* T4 = (const uint4*)g_t2;   // 16 uint4 per node row

    float acc[8];
#pragma unroll
    for (int j = 0; j < 8; j++) acc[j] = 0.f;
    acc_row(acc, T4[n * 16 + hl], dn * dn);   // self loop

    int e0 = g_rowoff[n], e1 = g_rowoff[n + 1];
    int e = e0;
    for (int r = (e1 - e0) & 3; r > 0; r--, e++) {
        int s = g_srcs[e];
        acc_row(acc, T4[(size_t)s * 16 + hl], g_ew[e]);
    }
    for (; e < e1; e += 4) {
        int s0 = g_srcs[e], s1 = g_srcs[e + 1], s2 = g_srcs[e + 2], s3 = g_srcs[e + 3];
        float w0e = g_ew[e], w1e = g_ew[e + 1], w2e = g_ew[e + 2], w3e = g_ew[e + 3];
        uint4 v0 = T4[(size_t)s0 * 16 + hl];
        uint4 v1 = T4[(size_t)s1 * 16 + hl];
        uint4 v2 = T4[(size_t)s2 * 16 + hl];
        uint4 v3 = T4[(size_t)s3 * 16 + hl];
        acc_row(acc, v0, w0e);
        acc_row(acc, v1, w1e);
        acc_row(acc, v2, w2e);
        acc_row(acc, v3, w3e);
    }

    {
        float4 b0 = ((const float4*)bias)[hl * 2];
        float4 b1 = ((const float4*)bias)[hl * 2 + 1];
        acc[0] += b0.x; acc[1] += b0.y; acc[2] += b0.z; acc[3] += b0.w;
        acc[4] += b1.x; acc[5] += b1.y; acc[6] += b1.z; acc[7] += b1.w;
    }

    float4* H4 = (float4*)g_h;
    if (mode == 0) {
        H4[n * 32 + hl * 2]     = make_float4(acc[0], acc[1], acc[2], acc[3]);
        H4[n * 32 + hl * 2 + 1] = make_float4(acc[4], acc[5], acc[6], acc[7]);
    } else {
        float s1 = 0.f, s2 = 0.f;
#pragma unroll
        for (int j = 0; j < 8; j++) { s1 += acc[j]; s2 += acc[j] * acc[j]; }
#pragma unroll
        for (int o = 8; o > 0; o >>= 1) {
            s1 += __shfl_xor_sync(0xffffffffu, s1, o);
            s2 += __shfl_xor_sync(0xffffffffu, s2, o);
        }
        float mu = s1 * (1.f / 128.f);
        float var = s2 * (1.f / 128.f) - mu * mu;
        float rs = rsqrtf(var + LN_EPS);
        float4 g0 = ((const float4*)gamma)[hl * 2];
        float4 g1 = ((const float4*)gamma)[hl * 2 + 1];
        float4 be0 = ((const float4*)beta)[hl * 2];
        float4 be1 = ((const float4*)beta)[hl * 2 + 1];
        float4 h0 = H4[n * 32 + hl * 2];
        float4 h1 = H4[n * 32 + hl * 2 + 1];
        h0.x += fmaxf((acc[0] - mu) * rs * g0.x + be0.x, 0.f);
        h0.y += fmaxf((acc[1] - mu) * rs * g0.y + be0.y, 0.f);
        h0.z += fmaxf((acc[2] - mu) * rs * g0.z + be0.z, 0.f);
        h0.w += fmaxf((acc[3] - mu) * rs * g0.w + be0.w, 0.f);
        h1.x += fmaxf((acc[4] - mu) * rs * g1.x + be1.x, 0.f);
        h1.y += fmaxf((acc[5] - mu) * rs * g1.y + be1.y, 0.f);
        h1.z += fmaxf((acc[6] - mu) * rs * g1.z + be1.z, 0.f);
        h1.w += fmaxf((acc[7] - mu) * rs * g1.w + be1.w, 0.f);
        H4[n * 32 + hl * 2] = h0;
        H4[n * 32 + hl * 2 + 1] = h1;
    }
}

// ==================== fused pool + readout ====================
__global__ void __launch_bounds__(128) readout_fused_kernel(
        const int* __restrict__ batch_idx,
        const float* __restrict__ W1, const float* __restrict__ b1,
        const float* __restrict__ W2, const float* __restrict__ b2,
        float* __restrict__ out) {
    __shared__ float yrow[128];
    __shared__ float partial[4];
    int g = blockIdx.x, j = threadIdx.x;

    int lo = 0, hi = N_NODES;
    while (lo < hi) { int m = (lo + hi) >> 1; if (batch_idx[m] < g) lo = m + 1; else hi = m; }
    int start = lo;
    lo = start; hi = N_NODES;
    while (lo < hi) { int m = (lo + hi) >> 1; if (batch_idx[m] < g + 1) lo = m + 1; else hi = m; }
    int end = lo;

    float acc = 0.f;
    int n = start;
    for (; n + 8 <= end; n += 8) {
        acc += g_h[(size_t)(n + 0) * D + j] + g_h[(size_t)(n + 1) * D + j]
             + g_h[(size_t)(n + 2) * D + j] + g_h[(size_t)(n + 3) * D + j]
             + g_h[(size_t)(n + 4) * D + j] + g_h[(size_t)(n + 5) * D + j]
             + g_h[(size_t)(n + 6) * D + j] + g_h[(size_t)(n + 7) * D + j];
    }
    for (; n < end; n++) acc += g_h[(size_t)n * D + j];
    yrow[j] = acc;
    __syncthreads();

    float m1 = 0.f;
#pragma unroll 8
    for (int k = 0; k < 128; k++) m1 += yrow[k] * W1[k * D + j];
    float z = fmaxf(m1 + b1[j], 0.f);
    float p = z * W2[j];
#pragma unroll
    for (int o = 16; o > 0; o >>= 1) p += __shfl_xor_sync(0xffffffffu, p, o);
    if ((j & 31) == 0) partial[j >> 5] = p;
    __syncthreads();
    if (j == 0) out[g] = partial[0] + partial[1] + partial[2] + partial[3] + b2[0];
}

// ==================== launch ====================
extern "C" void kernel_launch(void* const* d_in, const int* in_sizes, int n_in,
                              void* d_out, int out_size) {
    const float* x      = (const float*)d_in[0];
    const int*   ei     = (const int*)d_in[1];
    const int*   batch  = (const int*)d_in[2];
    const float* W_enc  = (const float*)d_in[3];
    const float* b_enc  = (const float*)d_in[4];
    const float* W_blk  = (const float*)d_in[5];
    const float* b_blk  = (const float*)d_in[6];
    const float* gamma  = (const float*)d_in[7];
    const float* beta   = (const float*)d_in[8];
    const float* W1     = (const float*)d_in[9];
    const float* b1     = (const float*)d_in[10];
    const float* W2     = (const float*)d_in[11];
    const float* b2     = (const float*)d_in[12];
    float* out = (float*)d_out;

    float* dh = nullptr;
    cudaGetSymbolAddress((void**)&dh, g_h);

    const int smem_gemm = (BM + 128) * PAD * 4;  // 101376 B
    cudaFuncSetAttribute(gemm_mma_kernel, cudaFuncAttributeMaxDynamicSharedMemorySize, smem_gemm);

    const int TB = 256;
    int nblk_nodes = (N_NODES + TB - 1) / TB;
    int nblk_edges = (N_EDGES + TB - 1) / TB;
    int nblk_gemm  = (N_NODES + BM - 1) / BM;
    int nblk_agg   = (N_NODES * 16 + TB - 1) / TB;

    // CSR build. Launch order matters for ncu (-s 5 -c 1 captures the 6th
    // kernel launch): zero(1), count(2), scan(3), fill(4), gemm(5), agg(6).
    zero_cnt_kernel<<<nblk_nodes, TB>>>();
    count_kernel<<<nblk_edges, TB>>>(ei);
    scan_kernel<<<1, 1024>>>();
    fill_kernel<<<nblk_edges, TB>>>(ei);

    // encoder
    gemm_mma_kernel<<<nblk_gemm, TB, smem_gemm>>>(x, W_enc);
    agg_kernel<<<nblk_agg, TB>>>(b_enc, nullptr, nullptr, 0);

    // standalone blk0
    gemm_mma_kernel<<<nblk_gemm, TB, smem_gemm>>>(dh, W_blk + 0 * D * D);
    agg_kernel<<<nblk_agg, TB>>>(b_blk + 0 * D, nullptr, nullptr, 0);

    // res blocks
    for (int l = 0; l < 3; l++) {
        gemm_mma_kernel<<<nblk_gemm, TB, smem_gemm>>>(dh, W_blk + l * D * D);
        agg_kernel<<<nblk_agg, TB>>>(b_blk + l * D, gamma + l * D, beta + l * D, 1);
    }

    // fused pool + readout
    readout_fused_kernel<<<N_GRAPHS, 128>>>(batch, W1, b1, W2, b2, out);
}

// round 12
// speedup vs baseline: 1.1278x; 1.1278x over previous
#include <cuda_runtime.h>
#include <cuda_fp16.h>
#include <cstdint>

#define N_NODES 50000
#define N_EDGES 800000
#define D 128
#define N_GRAPHS 128
#define LN_EPS 1e-5f

// ==================== device scratch ====================
__device__ uint2 g_t2[N_NODES * 32];     // messages, fp16: 128 ch = 256B per node
__device__ float g_h[N_NODES * D];       // node state (fp32)
__device__ int   g_cnt[N_NODES];
__device__ float g_dinv[N_NODES];
__device__ int   g_rowoff[N_NODES + 1];
__device__ int   g_rank[N_EDGES];        // per-edge rank within its dst row
__device__ int   g_srcs[N_EDGES];        // CSR src ids
__device__ float g_ew[N_EDGES];          // CSR edge weights (layer-invariant)

__device__ __forceinline__ float tf32r(float v) {
    uint32_t t;
    asm("cvt.rna.tf32.f32 %0, %1;" : "=r"(t) : "f"(v));
    return __uint_as_float(t);
}

__device__ __forceinline__ uint32_t pack_h2(float a, float b) {
    __half2 h = __floats2half2_rn(a, b);
    return *reinterpret_cast<uint32_t*>(&h);
}

__device__ __forceinline__ float2 h2f(uint32_t u) {
    return __half22float2(*reinterpret_cast<__half2*>(&u));
}

__device__ __forceinline__ void acc_row(float* acc, uint4 v, float w) {
    float2 q0 = h2f(v.x), q1 = h2f(v.y), q2 = h2f(v.z), q3 = h2f(v.w);
    acc[0] += q0.x * w; acc[1] += q0.y * w;
    acc[2] += q1.x * w; acc[3] += q1.y * w;
    acc[4] += q2.x * w; acc[5] += q2.y * w;
    acc[6] += q3.x * w; acc[7] += q3.y * w;
}

// ==================== CSR build ====================
// count also records each edge's rank within its dst -> fill needs no atomics.
__global__ void count_kernel(const int* __restrict__ edge_index) {
    int e = blockIdx.x * blockDim.x + threadIdx.x;
    if (e < N_EDGES) {
        int d = edge_index[N_EDGES + e];
        g_rank[e] = atomicAdd(&g_cnt[d], 1);
    }
}

__global__ void scan_kernel() {
    __shared__ int psum[1024];
    int t = threadIdx.x;
    const int CH = (N_NODES + 1023) / 1024;
    int base = t * CH, s = 0;
    for (int i = 0; i < CH; i++) {
        int idx = base + i;
        if (idx < N_NODES) s += g_cnt[idx];
    }
    psum[t] = s;
    __syncthreads();
    for (int o = 1; o < 1024; o <<= 1) {
        int v = 0;
        if (t >= o) v = psum[t - o];
        __syncthreads();
        psum[t] += v;
        __syncthreads();
    }
    int run = (t == 0) ? 0 : psum[t - 1];
    for (int i = 0; i < CH; i++) {
        int idx = base + i;
        if (idx < N_NODES) {
            int c = g_cnt[idx];
            g_rowoff[idx] = run;
            run += c;
            g_dinv[idx] = rsqrtf((float)(c + 1));
        }
    }
    if (t == 1023) g_rowoff[N_NODES] = psum[1023];
}

// atomic-free fill: pure bandwidth
__global__ void fill_kernel(const int* __restrict__ edge_index) {
    int e = blockIdx.x * blockDim.x + threadIdx.x;
    if (e < N_EDGES) {
        int s = edge_index[e];
        int d = edge_index[N_EDGES + e];
        int pos = g_rowoff[d] + g_rank[e];
        g_srcs[pos] = s;
        g_ew[pos] = g_dinv[s] * g_dinv[d];
    }
}

// ==================== tensor-core GEMM via mma.sync (tf32) ====================
// C[128x128] per CTA. K split into 4 chunks of 32, double-buffered in smem with
// register prefetch: DRAM streaming of A overlaps MMA compute.
#define APADW 36     // A chunk row stride (floats)
#define WPADW 136    // W chunk row stride (floats); 136%32=8 -> b-frag conflict-free
#define ABUF (128 * APADW)
#define WBUF (32 * WPADW)

__global__ void __launch_bounds__(256) gemm_mma_kernel(const float* __restrict__ A,
                                                       const float* __restrict__ W) {
    extern __shared__ float sm[];
    float* Ac = sm;                 // 2 x [128][APADW]
    float* Wc = sm + 2 * ABUF;      // 2 x [32][WPADW]
    int tid = threadIdx.x;
    int r0 = blockIdx.x * 128;

    const float4* A4 = (const float4*)A;
    const float4* W4 = (const float4*)W;

    float4 ra[4], rw[4];

    // --- chunk load (to registers) ---
    auto load_chunk = [&](int c) {
#pragma unroll
        for (int i = 0; i < 4; i++) {
            int idx = tid + i * 256;            // 1024 float4 of A chunk
            int row = idx >> 3, k4 = idx & 7;
            ra[i] = make_float4(0.f, 0.f, 0.f, 0.f);
            if (r0 + row < N_NODES) ra[i] = A4[(r0 + row) * 32 + c * 8 + k4];
        }
#pragma unroll
        for (int i = 0; i < 4; i++) {
            int idx = tid + i * 256;            // 1024 float4 of W chunk
            int k = idx >> 5, n4 = idx & 31;
            rw[i] = W4[(c * 32 + k) * 32 + n4];
        }
    };
    // --- chunk store (regs -> smem buffer b, with rna tf32 rounding) ---
    auto store_chunk = [&](int b) {
#pragma unroll
        for (int i = 0; i < 4; i++) {
            int idx = tid + i * 256;
            int row = idx >> 3, k4 = idx & 7;
            float4 v = ra[i];
            v.x = tf32r(v.x); v.y = tf32r(v.y); v.z = tf32r(v.z); v.w = tf32r(v.w);
            *(float4*)&Ac[b * ABUF + row * APADW + k4 * 4] = v;
        }
#pragma unroll
        for (int i = 0; i < 4; i++) {
            int idx = tid + i * 256;
            int k = idx >> 5, n4 = idx & 31;
            float4 v = rw[i];
            v.x = tf32r(v.x); v.y = tf32r(v.y); v.z = tf32r(v.z); v.w = tf32r(v.w);
            *(float4*)&Wc[b * WBUF + k * WPADW + n4 * 4] = v;
        }
    };

    int lane = tid & 31, wid = tid >> 5;
    int wm = (wid & 1) * 64;
    int wn = (wid >> 1) * 32;
    int gq = lane >> 2, tq = lane & 3;

    float acc[4][4][4];
#pragma unroll
    for (int mf = 0; mf < 4; mf++)
#pragma unroll
        for (int nf = 0; nf < 4; nf++)
#pragma unroll
            for (int j = 0; j < 4; j++) acc[mf][nf][j] = 0.f;

    load_chunk(0);
    store_chunk(0);
    __syncthreads();

#pragma unroll
    for (int c = 0; c < 4; c++) {
        if (c < 3) load_chunk(c + 1);          // LDG in flight during compute
        const float* Ab = &Ac[(c & 1) * ABUF];
        const float* Wb = &Wc[(c & 1) * WBUF];
#pragma unroll
        for (int k0 = 0; k0 < 32; k0 += 8) {
            uint32_t a[4][4];
#pragma unroll
            for (int mf = 0; mf < 4; mf++) {
                const float* ap = &Ab[(wm + mf * 16 + gq) * APADW + k0 + tq];
                a[mf][0] = __float_as_uint(ap[0]);
                a[mf][2] = __float_as_uint(ap[4]);
                a[mf][1] = __float_as_uint(ap[8 * APADW]);
                a[mf][3] = __float_as_uint(ap[8 * APADW + 4]);
            }
            uint32_t b[4][2];
#pragma unroll
            for (int nf = 0; nf < 4; nf++) {
                const float* bp = &Wb[(k0 + tq) * WPADW + wn + nf * 8 + gq];
                b[nf][0] = __float_as_uint(bp[0]);
                b[nf][1] = __float_as_uint(bp[4 * WPADW]);
            }
#pragma unroll
            for (int mf = 0; mf < 4; mf++)
#pragma unroll
                for (int nf = 0; nf < 4; nf++) {
                    asm volatile(
                        "mma.sync.aligned.m16n8k8.row.col.f32.tf32.tf32.f32 "
                        "{%0,%1,%2,%3}, {%4,%5,%6,%7}, {%8,%9}, {%0,%1,%2,%3};"
                        : "+f"(acc[mf][nf][0]), "+f"(acc[mf][nf][1]),
                          "+f"(acc[mf][nf][2]), "+f"(acc[mf][nf][3])
                        : "r"(a[mf][0]), "r"(a[mf][1]), "r"(a[mf][2]), "r"(a[mf][3]),
                          "r"(b[nf][0]), "r"(b[nf][1]));
                }
        }
        if (c < 3) {
            store_chunk((c + 1) & 1);          // other buffer: no hazard
            __syncthreads();
        }
    }

    uint32_t* T = (uint32_t*)g_t2;
#pragma unroll
    for (int mf = 0; mf < 4; mf++) {
        int row0 = r0 + wm + mf * 16 + gq;
#pragma unroll
        for (int nf = 0; nf < 4; nf++) {
            int c2 = (wn + nf * 8 + 2 * tq) >> 1;
            if (row0 < N_NODES)
                T[row0 * 64 + c2] = pack_h2(acc[mf][nf][0], acc[mf][nf][1]);
            if (row0 + 8 < N_NODES)
                T[(row0 + 8) * 64 + c2] = pack_h2(acc[mf][nf][2], acc[mf][nf][3]);
        }
    }
}

// ==================== aggregation: HALF-WARP per node ====================
__global__ void __launch_bounds__(256) agg_kernel(const float* __restrict__ bias,
                                                  const float* __restrict__ gamma,
                                                  const float* __restrict__ beta,
                                                  int mode) {
    int t = blockIdx.x * blockDim.x + threadIdx.x;
    int n = t >> 4;
    int hl = threadIdx.x & 15;
    if (n >= N_NODES) return;

    float dn = g_dinv[n];
    const uint4* T4 = (const uint4*)g_t2;   // 16 uint4 per node row

    float acc[8];
#pragma unroll
    for (int j = 0; j < 8; j++) acc[j] = 0.f;
    acc_row(acc, T4[n * 16 + hl], dn * dn);   // self loop

    int e0 = g_rowoff[n], e1 = g_rowoff[n + 1];
    int e = e0;
    for (int r = (e1 - e0) & 3; r > 0; r--, e++) {
        int s = g_srcs[e];
        acc_row(acc, T4[(size_t)s * 16 + hl], g_ew[e]);
    }
    for (; e < e1; e += 4) {
        int s0 = g_srcs[e], s1 = g_srcs[e + 1], s2 = g_srcs[e + 2], s3 = g_srcs[e + 3];
        float w0e = g_ew[e], w1e = g_ew[e + 1], w2e = g_ew[e + 2], w3e = g_ew[e + 3];
        uint4 v0 = T4[(size_t)s0 * 16 + hl];
        uint4 v1 = T4[(size_t)s1 * 16 + hl];
        uint4 v2 = T4[(size_t)s2 * 16 + hl];
        uint4 v3 = T4[(size_t)s3 * 16 + hl];
        acc_row(acc, v0, w0e);
        acc_row(acc, v1, w1e);
        acc_row(acc, v2, w2e);
        acc_row(acc, v3, w3e);
    }

    {
        float4 b0 = ((const float4*)bias)[hl * 2];
        float4 b1 = ((const float4*)bias)[hl * 2 + 1];
        acc[0] += b0.x; acc[1] += b0.y; acc[2] += b0.z; acc[3] += b0.w;
        acc[4] += b1.x; acc[5] += b1.y; acc[6] += b1.z; acc[7] += b1.w;
    }

    float4* H4 = (float4*)g_h;
    if (mode == 0) {
        H4[n * 32 + hl * 2]     = make_float4(acc[0], acc[1], acc[2], acc[3]);
        H4[n * 32 + hl * 2 + 1] = make_float4(acc[4], acc[5], acc[6], acc[7]);
    } else {
        float s1 = 0.f, s2 = 0.f;
#pragma unroll
        for (int j = 0; j < 8; j++) { s1 += acc[j]; s2 += acc[j] * acc[j]; }
#pragma unroll
        for (int o = 8; o > 0; o >>= 1) {
            s1 += __shfl_xor_sync(0xffffffffu, s1, o);
            s2 += __shfl_xor_sync(0xffffffffu, s2, o);
        }
        float mu = s1 * (1.f / 128.f);
        float var = s2 * (1.f / 128.f) - mu * mu;
        float rs = rsqrtf(var + LN_EPS);
        float4 g0 = ((const float4*)gamma)[hl * 2];
        float4 g1 = ((const float4*)gamma)[hl * 2 + 1];
        float4 be0 = ((const float4*)beta)[hl * 2];
        float4 be1 = ((const float4*)beta)[hl * 2 + 1];
        float4 h0 = H4[n * 32 + hl * 2];
        float4 h1 = H4[n * 32 + hl * 2 + 1];
        h0.x += fmaxf((acc[0] - mu) * rs * g0.x + be0.x, 0.f);
        h0.y += fmaxf((acc[1] - mu) * rs * g0.y + be0.y, 0.f);
        h0.z += fmaxf((acc[2] - mu) * rs * g0.z + be0.z, 0.f);
        h0.w += fmaxf((acc[3] - mu) * rs * g0.w + be0.w, 0.f);
        h1.x += fmaxf((acc[4] - mu) * rs * g1.x + be1.x, 0.f);
        h1.y += fmaxf((acc[5] - mu) * rs * g1.y + be1.y, 0.f);
        h1.z += fmaxf((acc[6] - mu) * rs * g1.z + be1.z, 0.f);
        h1.w += fmaxf((acc[7] - mu) * rs * g1.w + be1.w, 0.f);
        H4[n * 32 + hl * 2] = h0;
        H4[n * 32 + hl * 2 + 1] = h1;
    }
}

// ==================== fused pool + readout ====================
__global__ void __launch_bounds__(128) readout_fused_kernel(
        const int* __restrict__ batch_idx,
        const float* __restrict__ W1, const float* __restrict__ b1,
        const float* __restrict__ W2, const float* __restrict__ b2,
        float* __restrict__ out) {
    __shared__ float yrow[128];
    __shared__ float partial[4];
    int g = blockIdx.x, j = threadIdx.x;

    int lo = 0, hi = N_NODES;
    while (lo < hi) { int m = (lo + hi) >> 1; if (batch_idx[m] < g) lo = m + 1; else hi = m; }
    int start = lo;
    lo = start; hi = N_NODES;
    while (lo < hi) { int m = (lo + hi) >> 1; if (batch_idx[m] < g + 1) lo = m + 1; else hi = m; }
    int end = lo;

    float acc = 0.f;
    int n = start;
    for (; n + 8 <= end; n += 8) {
        acc += g_h[(size_t)(n + 0) * D + j] + g_h[(size_t)(n + 1) * D + j]
             + g_h[(size_t)(n + 2) * D + j] + g_h[(size_t)(n + 3) * D + j]
             + g_h[(size_t)(n + 4) * D + j] + g_h[(size_t)(n + 5) * D + j]
             + g_h[(size_t)(n + 6) * D + j] + g_h[(size_t)(n + 7) * D + j];
    }
    for (; n < end; n++) acc += g_h[(size_t)n * D + j];
    yrow[j] = acc;
    __syncthreads();

    float m1 = 0.f;
#pragma unroll 8
    for (int k = 0; k < 128; k++) m1 += yrow[k] * W1[k * D + j];
    float z = fmaxf(m1 + b1[j], 0.f);
    float p = z * W2[j];
#pragma unroll
    for (int o = 16; o > 0; o >>= 1) p += __shfl_xor_sync(0xffffffffu, p, o);
    if ((j & 31) == 0) partial[j >> 5] = p;
    __syncthreads();
    if (j == 0) out[g] = partial[0] + partial[1] + partial[2] + partial[3] + b2[0];
}

// ==================== launch ====================
extern "C" void kernel_launch(void* const* d_in, const int* in_sizes, int n_in,
                              void* d_out, int out_size) {
    const float* x      = (const float*)d_in[0];
    const int*   ei     = (const int*)d_in[1];
    const int*   batch  = (const int*)d_in[2];
    const float* W_enc  = (const float*)d_in[3];
    const float* b_enc  = (const float*)d_in[4];
    const float* W_blk  = (const float*)d_in[5];
    const float* b_blk  = (const float*)d_in[6];
    const float* gamma  = (const float*)d_in[7];
    const float* beta   = (const float*)d_in[8];
    const float* W1     = (const float*)d_in[9];
    const float* b1     = (const float*)d_in[10];
    const float* W2     = (const float*)d_in[11];
    const float* b2     = (const float*)d_in[12];
    float* out = (float*)d_out;

    float* dh = nullptr;
    cudaGetSymbolAddress((void**)&dh, g_h);
    int* dcnt = nullptr;
    cudaGetSymbolAddress((void**)&dcnt, g_cnt);

    const int smem_gemm = (2 * ABUF + 2 * WBUF) * 4;  // 71680 B
    cudaFuncSetAttribute(gemm_mma_kernel, cudaFuncAttributeMaxDynamicSharedMemorySize, smem_gemm);

    const int TB = 256;
    int nblk_edges = (N_EDGES + TB - 1) / TB;
    int nblk_gemm  = (N_NODES + 127) / 128;
    int nblk_agg   = (N_NODES * 16 + TB - 1) / TB;

    // CSR build. Kernel launch order: count(1), scan(2), fill(3), gemm(4)
    // -> ncu capture slot (4th kernel) lands on the new GEMM.
    cudaMemsetAsync(dcnt, 0, N_NODES * sizeof(int));
    count_kernel<<<nblk_edges, TB>>>(ei);
    scan_kernel<<<1, 1024>>>();
    fill_kernel<<<nblk_edges, TB>>>(ei);

    // encoder
    gemm_mma_kernel<<<nblk_gemm, TB, smem_gemm>>>(x, W_enc);
    agg_kernel<<<nblk_agg, TB>>>(b_enc, nullptr, nullptr, 0);

    // standalone blk0
    gemm_mma_kernel<<<nblk_gemm, TB, smem_gemm>>>(dh, W_blk + 0 * D * D);
    agg_kernel<<<nblk_agg, TB>>>(b_blk + 0 * D, nullptr, nullptr, 0);

    // res blocks
    for (int l = 0; l < 3; l++) {
        gemm_mma_kernel<<<nblk_gemm, TB, smem_gemm>>>(dh, W_blk + l * D * D);
        agg_kernel<<<nblk_agg, TB>>>(b_blk + l * D, gamma + l * D, beta + l * D, 1);
    }

    // fused pool + readout
    readout_fused_kernel<<<N_GRAPHS, 128>>>(batch, W1, b1, W2, b2, out);
}

// round 13
// speedup vs baseline: 1.1534x; 1.0227x over previous
#include <cuda_runtime.h>
#include <cuda_fp16.h>
#include <cstdint>

#define N_NODES 50000
#define N_EDGES 800000
#define D 128
#define N_GRAPHS 128
#define LN_EPS 1e-5f

// ==================== device scratch ====================
__device__ uint2 g_t2[N_NODES * 32];     // messages, fp16: 128 ch = 256B per node
__device__ float g_h[N_NODES * D];       // node state (fp32)
__device__ int   g_cnt[N_NODES];
__device__ float g_dinv[N_NODES];
__device__ int   g_rowoff[N_NODES + 1];
__device__ int   g_rank[N_EDGES];        // per-edge rank within its dst row
__device__ int   g_srcs[N_EDGES];        // CSR src ids
__device__ float g_ew[N_EDGES];          // CSR edge weights (layer-invariant)

__device__ __forceinline__ float tf32r(float v) {
    uint32_t t;
    asm("cvt.rna.tf32.f32 %0, %1;" : "=r"(t) : "f"(v));
    return __uint_as_float(t);
}

__device__ __forceinline__ uint32_t tf32u(float v) {
    uint32_t t;
    asm("cvt.rna.tf32.f32 %0, %1;" : "=r"(t) : "f"(v));
    return t;
}

__device__ __forceinline__ uint32_t pack_h2(float a, float b) {
    __half2 h = __floats2half2_rn(a, b);
    return *reinterpret_cast<uint32_t*>(&h);
}

__device__ __forceinline__ float2 h2f(uint32_t u) {
    return __half22float2(*reinterpret_cast<__half2*>(&u));
}

__device__ __forceinline__ void acc_row(float* acc, uint4 v, float w) {
    float2 q0 = h2f(v.x), q1 = h2f(v.y), q2 = h2f(v.z), q3 = h2f(v.w);
    acc[0] += q0.x * w; acc[1] += q0.y * w;
    acc[2] += q1.x * w; acc[3] += q1.y * w;
    acc[4] += q2.x * w; acc[5] += q2.y * w;
    acc[6] += q3.x * w; acc[7] += q3.y * w;
}

// ==================== CSR build ====================
__global__ void count_kernel(const int* __restrict__ edge_index) {
    int e = blockIdx.x * blockDim.x + threadIdx.x;
    if (e < N_EDGES) {
        int d = edge_index[N_EDGES + e];
        g_rank[e] = atomicAdd(&g_cnt[d], 1);
    }
}

__global__ void scan_kernel() {
    __shared__ int psum[1024];
    int t = threadIdx.x;
    const int CH = (N_NODES + 1023) / 1024;
    int base = t * CH, s = 0;
    for (int i = 0; i < CH; i++) {
        int idx = base + i;
        if (idx < N_NODES) s += g_cnt[idx];
    }
    psum[t] = s;
    __syncthreads();
    for (int o = 1; o < 1024; o <<= 1) {
        int v = 0;
        if (t >= o) v = psum[t - o];
        __syncthreads();
        psum[t] += v;
        __syncthreads();
    }
    int run = (t == 0) ? 0 : psum[t - 1];
    for (int i = 0; i < CH; i++) {
        int idx = base + i;
        if (idx < N_NODES) {
            int c = g_cnt[idx];
            g_rowoff[idx] = run;
            run += c;
            g_dinv[idx] = rsqrtf((float)(c + 1));
        }
    }
    if (t == 1023) g_rowoff[N_NODES] = psum[1023];
}

__global__ void fill_kernel(const int* __restrict__ edge_index) {
    int e = blockIdx.x * blockDim.x + threadIdx.x;
    if (e < N_EDGES) {
        int s = edge_index[e];
        int d = edge_index[N_EDGES + e];
        int pos = g_rowoff[d] + g_rank[e];
        g_srcs[pos] = s;
        g_ew[pos] = g_dinv[s] * g_dinv[d];
    }
}

// ==================== tensor-core GEMM via mma.sync (tf32) ====================
// C[128x128] per CTA. W staged whole (rounded). A streamed via cp.async in 4
// double-buffered K-chunks (no register staging -> low regs -> 2 CTAs/SM).
// A rounded to tf32 at fragment-load time (free of memory cost).
#define APADW 36     // A chunk row stride (floats); conflict-free a-frag LDS
#define WPADW 136    // W row stride (floats); 136%32=8 -> conflict-free b-frag LDS
#define ABUF (128 * APADW)

__global__ void __launch_bounds__(256, 2) gemm_mma_kernel(const float* __restrict__ A,
                                                          const float* __restrict__ W) {
    extern __shared__ float sm[];
    float* Ws = sm;                    // [128][WPADW]
    float* Ac = sm + 128 * WPADW;      // 2 x [128][APADW]
    int tid = threadIdx.x;
    int r0 = blockIdx.x * 128;

    const float4* A4 = (const float4*)A;

    // issue A-chunk c prefetch into buffer b (cp.async, zero-fill OOB rows)
    auto prefetch = [&](int c, int b) {
#pragma unroll
        for (int i = 0; i < 4; i++) {
            int idx = tid + i * 256;            // 1024 float4 per chunk
            int row = idx >> 3, k4 = idx & 7;
            int gr = r0 + row;
            const float4* src = &A4[(size_t)(gr < N_NODES ? gr : N_NODES - 1) * 32 + c * 8 + k4];
            uint32_t dst = (uint32_t)__cvta_generic_to_shared(&Ac[b * ABUF + row * APADW + k4 * 4]);
            int sz = (gr < N_NODES) ? 16 : 0;
            asm volatile("cp.async.cg.shared.global [%0], [%1], 16, %2;"
                         :: "r"(dst), "l"(src), "r"(sz) : "memory");
        }
        asm volatile("cp.async.commit_group;" ::: "memory");
    };

    prefetch(0, 0);

    // stage W whole (rounded), overlapping with the first A chunk in flight
    {
        const float4* W4 = (const float4*)W;
#pragma unroll
        for (int i = 0; i < 16; i++) {
            int idx = tid + i * 256;            // 4096 float4
            int k = idx >> 5, n4 = idx & 31;
            float4 v = W4[idx];
            v.x = tf32r(v.x); v.y = tf32r(v.y); v.z = tf32r(v.z); v.w = tf32r(v.w);
            *(float4*)&Ws[k * WPADW + n4 * 4] = v;
        }
    }

    int lane = tid & 31, wid = tid >> 5;
    int wm = (wid & 1) * 64;
    int wn = (wid >> 1) * 32;
    int gq = lane >> 2, tq = lane & 3;

    float acc[4][4][4];
#pragma unroll
    for (int mf = 0; mf < 4; mf++)
#pragma unroll
        for (int nf = 0; nf < 4; nf++)
#pragma unroll
            for (int j = 0; j < 4; j++) acc[mf][nf][j] = 0.f;

#pragma unroll
    for (int c = 0; c < 4; c++) {
        if (c < 3) prefetch(c + 1, (c + 1) & 1);
        if (c < 3) asm volatile("cp.async.wait_group 1;" ::: "memory");
        else       asm volatile("cp.async.wait_group 0;" ::: "memory");
        __syncthreads();

        const float* Ab = &Ac[(c & 1) * ABUF];
#pragma unroll
        for (int k0 = 0; k0 < 32; k0 += 8) {
            uint32_t a[4][4];
#pragma unroll
            for (int mf = 0; mf < 4; mf++) {
                const float* ap = &Ab[(wm + mf * 16 + gq) * APADW + k0 + tq];
                a[mf][0] = tf32u(ap[0]);
                a[mf][2] = tf32u(ap[4]);
                a[mf][1] = tf32u(ap[8 * APADW]);
                a[mf][3] = tf32u(ap[8 * APADW + 4]);
            }
            uint32_t b[4][2];
#pragma unroll
            for (int nf = 0; nf < 4; nf++) {
                const float* bp = &Ws[(c * 32 + k0 + tq) * WPADW + wn + nf * 8 + gq];
                b[nf][0] = __float_as_uint(bp[0]);
                b[nf][1] = __float_as_uint(bp[4 * WPADW]);
            }
#pragma unroll
            for (int mf = 0; mf < 4; mf++)
#pragma unroll
                for (int nf = 0; nf < 4; nf++) {
                    asm volatile(
                        "mma.sync.aligned.m16n8k8.row.col.f32.tf32.tf32.f32 "
                        "{%0,%1,%2,%3}, {%4,%5,%6,%7}, {%8,%9}, {%0,%1,%2,%3};"
                        : "+f"(acc[mf][nf][0]), "+f"(acc[mf][nf][1]),
                          "+f"(acc[mf][nf][2]), "+f"(acc[mf][nf][3])
                        : "r"(a[mf][0]), "r"(a[mf][1]), "r"(a[mf][2]), "r"(a[mf][3]),
                          "r"(b[nf][0]), "r"(b[nf][1]));
                }
        }
        if (c < 3) __syncthreads();   // all reads of this buffer done before overwrite
    }

    uint32_t* T = (uint32_t*)g_t2;
#pragma unroll
    for (int mf = 0; mf < 4; mf++) {
        int row0 = r0 + wm + mf * 16 + gq;
#pragma unroll
        for (int nf = 0; nf < 4; nf++) {
            int c2 = (wn + nf * 8 + 2 * tq) >> 1;
            if (row0 < N_NODES)
                T[row0 * 64 + c2] = pack_h2(acc[mf][nf][0], acc[mf][nf][1]);
            if (row0 + 8 < N_NODES)
                T[(row0 + 8) * 64 + c2] = pack_h2(acc[mf][nf][2], acc[mf][nf][3]);
        }
    }
}

// ==================== aggregation: HALF-WARP per node ====================
__global__ void __launch_bounds__(256) agg_kernel(const float* __restrict__ bias,
                                                  const float* __restrict__ gamma,
                                                  const float* __restrict__ beta,
                                                  int mode) {
    int t = blockIdx.x * blockDim.x + threadIdx.x;
    int n = t >> 4;
    int hl = threadIdx.x & 15;
    if (n >= N_NODES) return;

    float dn = g_dinv[n];
    const uint4* T4 = (const uint4*)g_t2;   // 16 uint4 per node row

    float acc[8];
#pragma unroll
    for (int j = 0; j < 8; j++) acc[j] = 0.f;
    acc_row(acc, T4[n * 16 + hl], dn * dn);   // self loop

    int e0 = g_rowoff[n], e1 = g_rowoff[n + 1];
    int e = e0;
    for (int r = (e1 - e0) & 3; r > 0; r--, e++) {
        int s = g_srcs[e];
        acc_row(acc, T4[(size_t)s * 16 + hl], g_ew[e]);
    }
    for (; e < e1; e += 4) {
        int s0 = g_srcs[e], s1 = g_srcs[e + 1], s2 = g_srcs[e + 2], s3 = g_srcs[e + 3];
        float w0e = g_ew[e], w1e = g_ew[e + 1], w2e = g_ew[e + 2], w3e = g_ew[e + 3];
        uint4 v0 = T4[(size_t)s0 * 16 + hl];
        uint4 v1 = T4[(size_t)s1 * 16 + hl];
        uint4 v2 = T4[(size_t)s2 * 16 + hl];
        uint4 v3 = T4[(size_t)s3 * 16 + hl];
        acc_row(acc, v0, w0e);
        acc_row(acc, v1, w1e);
        acc_row(acc, v2, w2e);
        acc_row(acc, v3, w3e);
    }

    {
        float4 b0 = ((const float4*)bias)[hl * 2];
        float4 b1 = ((const float4*)bias)[hl * 2 + 1];
        acc[0] += b0.x; acc[1] += b0.y; acc[2] += b0.z; acc[3] += b0.w;
        acc[4] += b1.x; acc[5] += b1.y; acc[6] += b1.z; acc[7] += b1.w;
    }

    float4* H4 = (float4*)g_h;
    if (mode == 0) {
        H4[n * 32 + hl * 2]     = make_float4(acc[0], acc[1], acc[2], acc[3]);
        H4[n * 32 + hl * 2 + 1] = make_float4(acc[4], acc[5], acc[6], acc[7]);
    } else {
        float s1 = 0.f, s2 = 0.f;
#pragma unroll
        for (int j = 0; j < 8; j++) { s1 += acc[j]; s2 += acc[j] * acc[j]; }
#pragma unroll
        for (int o = 8; o > 0; o >>= 1) {
            s1 += __shfl_xor_sync(0xffffffffu, s1, o);
            s2 += __shfl_xor_sync(0xffffffffu, s2, o);
        }
        float mu = s1 * (1.f / 128.f);
        float var = s2 * (1.f / 128.f) - mu * mu;
        float rs = rsqrtf(var + LN_EPS);
        float4 g0 = ((const float4*)gamma)[hl * 2];
        float4 g1 = ((const float4*)gamma)[hl * 2 + 1];
        float4 be0 = ((const float4*)beta)[hl * 2];
        float4 be1 = ((const float4*)beta)[hl * 2 + 1];
        float4 h0 = H4[n * 32 + hl * 2];
        float4 h1 = H4[n * 32 + hl * 2 + 1];
        h0.x += fmaxf((acc[0] - mu) * rs * g0.x + be0.x, 0.f);
        h0.y += fmaxf((acc[1] - mu) * rs * g0.y + be0.y, 0.f);
        h0.z += fmaxf((acc[2] - mu) * rs * g0.z + be0.z, 0.f);
        h0.w += fmaxf((acc[3] - mu) * rs * g0.w + be0.w, 0.f);
        h1.x += fmaxf((acc[4] - mu) * rs * g1.x + be1.x, 0.f);
        h1.y += fmaxf((acc[5] - mu) * rs * g1.y + be1.y, 0.f);
        h1.z += fmaxf((acc[6] - mu) * rs * g1.z + be1.z, 0.f);
        h1.w += fmaxf((acc[7] - mu) * rs * g1.w + be1.w, 0.f);
        H4[n * 32 + hl * 2] = h0;
        H4[n * 32 + hl * 2 + 1] = h1;
    }
}

// ==================== fused pool + readout ====================
__global__ void __launch_bounds__(128) readout_fused_kernel(
        const int* __restrict__ batch_idx,
        const float* __restrict__ W1, const float* __restrict__ b1,
        const float* __restrict__ W2, const float* __restrict__ b2,
        float* __restrict__ out) {
    __shared__ float yrow[128];
    __shared__ float partial[4];
    int g = blockIdx.x, j = threadIdx.x;

    int lo = 0, hi = N_NODES;
    while (lo < hi) { int m = (lo + hi) >> 1; if (batch_idx[m] < g) lo = m + 1; else hi = m; }
    int start = lo;
    lo = start; hi = N_NODES;
    while (lo < hi) { int m = (lo + hi) >> 1; if (batch_idx[m] < g + 1) lo = m + 1; else hi = m; }
    int end = lo;

    float acc = 0.f;
    int n = start;
    for (; n + 8 <= end; n += 8) {
        acc += g_h[(size_t)(n + 0) * D + j] + g_h[(size_t)(n + 1) * D + j]
             + g_h[(size_t)(n + 2) * D + j] + g_h[(size_t)(n + 3) * D + j]
             + g_h[(size_t)(n + 4) * D + j] + g_h[(size_t)(n + 5) * D + j]
             + g_h[(size_t)(n + 6) * D + j] + g_h[(size_t)(n + 7) * D + j];
    }
    for (; n < end; n++) acc += g_h[(size_t)n * D + j];
    yrow[j] = acc;
    __syncthreads();

    float m1 = 0.f;
#pragma unroll 8
    for (int k = 0; k < 128; k++) m1 += yrow[k] * W1[k * D + j];
    float z = fmaxf(m1 + b1[j], 0.f);
    float p = z * W2[j];
#pragma unroll
    for (int o = 16; o > 0; o >>= 1) p += __shfl_xor_sync(0xffffffffu, p, o);
    if ((j & 31) == 0) partial[j >> 5] = p;
    __syncthreads();
    if (j == 0) out[g] = partial[0] + partial[1] + partial[2] + partial[3] + b2[0];
}

// ==================== launch ====================
extern "C" void kernel_launch(void* const* d_in, const int* in_sizes, int n_in,
                              void* d_out, int out_size) {
    const float* x      = (const float*)d_in[0];
    const int*   ei     = (const int*)d_in[1];
    const int*   batch  = (const int*)d_in[2];
    const float* W_enc  = (const float*)d_in[3];
    const float* b_enc  = (const float*)d_in[4];
    const float* W_blk  = (const float*)d_in[5];
    const float* b_blk  = (const float*)d_in[6];
    const float* gamma  = (const float*)d_in[7];
    const float* beta   = (const float*)d_in[8];
    const float* W1     = (const float*)d_in[9];
    const float* b1     = (const float*)d_in[10];
    const float* W2     = (const float*)d_in[11];
    const float* b2     = (const float*)d_in[12];
    float* out = (float*)d_out;

    float* dh = nullptr;
    cudaGetSymbolAddress((void**)&dh, g_h);
    int* dcnt = nullptr;
    cudaGetSymbolAddress((void**)&dcnt, g_cnt);

    const int smem_gemm = (128 * WPADW + 2 * ABUF) * 4;  // 106496 B
    cudaFuncSetAttribute(gemm_mma_kernel, cudaFuncAttributeMaxDynamicSharedMemorySize, smem_gemm);

    const int TB = 256;
    int nblk_edges = (N_EDGES + TB - 1) / TB;
    int nblk_gemm  = (N_NODES + 127) / 128;
    int nblk_agg   = (N_NODES * 16 + TB - 1) / TB;

    // CSR build. Kernel order: count(1), scan(2), fill(3), gemm(4) -> ncu
    // capture slot (4th kernel) verifies GEMM v4.
    cudaMemsetAsync(dcnt, 0, N_NODES * sizeof(int));
    count_kernel<<<nblk_edges, TB>>>(ei);
    scan_kernel<<<1, 1024>>>();
    fill_kernel<<<nblk_edges, TB>>>(ei);

    // encoder
    gemm_mma_kernel<<<nblk_gemm, TB, smem_gemm>>>(x, W_enc);
    agg_kernel<<<nblk_agg, TB>>>(b_enc, nullptr, nullptr, 0);

    // standalone blk0
    gemm_mma_kernel<<<nblk_gemm, TB, smem_gemm>>>(dh, W_blk + 0 * D * D);
    agg_kernel<<<nblk_agg, TB>>>(b_blk + 0 * D, nullptr, nullptr, 0);

    // res blocks
    for (int l = 0; l < 3; l++) {
        gemm_mma_kernel<<<nblk_gemm, TB, smem_gemm>>>(dh, W_blk + l * D * D);
        agg_kernel<<<nblk_agg, TB>>>(b_blk + l * D, gamma + l * D, beta + l * D, 1);
    }

    // fused pool + readout
    readout_fused_kernel<<<N_GRAPHS, 128>>>(batch, W1, b1, W2, b2, out);
}